// round 2
// baseline (speedup 1.0000x reference)
#include <cuda_runtime.h>
#include <math.h>

// ============================================================================
// CrossAttention (SAGAN-style spatial self-attention), fp32 baseline.
//   B=4, C=256, W=H=64 -> N=4096, DK=32.
//   Kernel 1: fused QKV projection (1x1 convs == channel GEMMs)
//             g_qkv[b][n][0:32)=q, [32:64)=k, [64:320)=v   (n-major layout)
//   Kernel 2: flash attention per (batch, 64-query tile) + residual add.
// ============================================================================

#define DEV_INLINE __device__ __forceinline__

constexpr int B    = 4;
constexpr int C    = 256;
constexpr int N    = 4096;
constexpr int DK   = 32;
constexpr int DTOT = 320;                       // 32 q + 32 k + 256 v
constexpr float SCALE = 0.17677669529663687f;   // 1/sqrt(32)

// Scratch: (B, N, 320) fp32 = 21 MB
__device__ float g_qkv[(size_t)B * N * DTOT];

// ----------------------------------------------------------------------------
// Kernel 1: projection.  out[b][n][d] = sum_c W[d][c] * x[b][c][n] + bias[d]
// CTA = (64 n) x (64 d), K=256.  256 threads as 16(tn) x 16(td), 4x4 microtile.
// ----------------------------------------------------------------------------
__global__ __launch_bounds__(256) void proj_kernel(
    const float* __restrict__ x,
    const float* __restrict__ Wq, const float* __restrict__ bq,
    const float* __restrict__ Wk, const float* __restrict__ bk,
    const float* __restrict__ Wv, const float* __restrict__ bv)
{
    __shared__ float xs[64][64];   // [c][n]
    __shared__ float ws[64][64];   // [d][c]

    const int tid = threadIdx.x;
    const int n0  = blockIdx.x * 64;
    const int d0  = blockIdx.y * 64;
    const int b   = blockIdx.z;
    const int tn  = tid & 15;
    const int td  = tid >> 4;

    float acc[4][4];
    #pragma unroll
    for (int i = 0; i < 4; i++)
        #pragma unroll
        for (int j = 0; j < 4; j++) acc[i][j] = 0.f;

    for (int cc = 0; cc < C; cc += 64) {
        // load x tile: x[b][cc+c][n0..n0+64)  (rows contiguous in n -> coalesced)
        #pragma unroll
        for (int r = 0; r < 4; r++) {
            int i  = tid + r * 256;        // float4 index 0..1023
            int c  = i >> 4;
            int nn = (i & 15) * 4;
            *reinterpret_cast<float4*>(&xs[c][nn]) =
                *reinterpret_cast<const float4*>(
                    &x[(size_t)(b * C + cc + c) * N + n0 + nn]);
        }
        // load W tile into ws[d][c] (natural layout; rows contiguous -> coalesced)
        #pragma unroll
        for (int r = 0; r < 4; r++) {
            int i  = tid + r * 256;
            int d  = i >> 4;
            int c4 = (i & 15) * 4;
            int gd = d0 + d;
            const float* src;
            if (gd < DK)            src = Wq + (size_t)gd * C;
            else if (gd < 2 * DK)   src = Wk + (size_t)(gd - DK) * C;
            else                    src = Wv + (size_t)(gd - 2 * DK) * C;
            *reinterpret_cast<float4*>(&ws[d][c4]) =
                *reinterpret_cast<const float4*>(&src[cc + c4]);
        }
        __syncthreads();

        #pragma unroll 4
        for (int c = 0; c < 64; c++) {
            float4 xv = *reinterpret_cast<const float4*>(&xs[c][4 * tn]);
            float xvv[4] = {xv.x, xv.y, xv.z, xv.w};
            float wv[4];
            #pragma unroll
            for (int j = 0; j < 4; j++) wv[j] = ws[4 * td + j][c];  // broadcast
            #pragma unroll
            for (int i = 0; i < 4; i++)
                #pragma unroll
                for (int j = 0; j < 4; j++) acc[i][j] += xvv[i] * wv[j];
        }
        __syncthreads();
    }

    // bias + store (n-major layout)
    float bias[4];
    #pragma unroll
    for (int j = 0; j < 4; j++) {
        int gd = d0 + 4 * td + j;
        bias[j] = (gd < DK) ? bq[gd] : (gd < 2 * DK) ? bk[gd - DK] : bv[gd - 2 * DK];
    }
    #pragma unroll
    for (int i = 0; i < 4; i++) {
        float4 v;
        v.x = acc[i][0] + bias[0];
        v.y = acc[i][1] + bias[1];
        v.z = acc[i][2] + bias[2];
        v.w = acc[i][3] + bias[3];
        *reinterpret_cast<float4*>(
            &g_qkv[((size_t)b * N + n0 + 4 * tn + i) * DTOT + d0 + 4 * td]) = v;
    }
}

// ----------------------------------------------------------------------------
// Kernel 2: flash attention.  CTA = (batch b, 64-query tile), 256 threads.
//   S phase mapping : thread -> (mS = tid>>2, 16 keys), shfl softmax in 4-groups
//   PV phase mapping: thread -> (m in {pm, pm+32}, 32 channels, cq = warp id)
//                     V smem reads are warp-uniform (pure broadcast).
// smem (dynamic, 101,888 B):
//   sQ[64][36] sK[64][36] sP[64][68] sV[64][256] sAlpha[64] sSum[64]
// ----------------------------------------------------------------------------
constexpr int SQ_OFF = 0;       // 64*36 = 2304
constexpr int SK_OFF = 2304;    // 64*36 = 2304
constexpr int SP_OFF = 4608;    // 64*68 = 4352
constexpr int SV_OFF = 8960;    // 64*256 = 16384
constexpr int SA_OFF = 25344;   // 64
constexpr int SS_OFF = 25408;   // 64
constexpr int SMEM_FLOATS = 25472;
constexpr int SMEM_BYTES  = SMEM_FLOATS * 4;    // 101,888

DEV_INLINE void pv_step(float pa, float pb, const float* vrow,
                        float4* o0, float4* o1)
{
    #pragma unroll
    for (int j = 0; j < 8; j++) {
        float4 v = *reinterpret_cast<const float4*>(vrow + 4 * j);
        o0[j].x += pa * v.x; o0[j].y += pa * v.y;
        o0[j].z += pa * v.z; o0[j].w += pa * v.w;
        o1[j].x += pb * v.x; o1[j].y += pb * v.y;
        o1[j].z += pb * v.z; o1[j].w += pb * v.w;
    }
}

__global__ __launch_bounds__(256) void flash_kernel(
    const float* __restrict__ x, float* __restrict__ out)
{
    extern __shared__ float sm[];
    float* sQ     = sm + SQ_OFF;
    float* sK     = sm + SK_OFF;
    float* sP     = sm + SP_OFF;
    float* sV     = sm + SV_OFF;
    float* sAlpha = sm + SA_OFF;
    float* sSum   = sm + SS_OFF;

    const int tid = threadIdx.x;
    const int b   = blockIdx.y;
    const int m0  = blockIdx.x * 64;
    const size_t base = (size_t)b * N;

    // load Q tile (rows padded to 36 floats -> conflict-free strided reads)
    for (int idx = tid; idx < 64 * 32; idx += 256) {
        int m = idx >> 5, d = idx & 31;
        sQ[m * 36 + d] = g_qkv[(base + m0 + m) * DTOT + d];
    }
    __syncthreads();

    // ---- S-phase identity: row mS, key quarter nq ----
    const int mS = tid >> 2, nq = tid & 3;
    float4 q4[8];
    #pragma unroll
    for (int d4 = 0; d4 < 8; d4++)
        q4[d4] = *reinterpret_cast<const float4*>(&sQ[mS * 36 + 4 * d4]);

    float Mrow = -1e30f, Lrow = 0.f;

    // ---- PV-phase identity: rows {pm, pm+32}, channel block cq ----
    const int pm = tid & 31, cq = tid >> 5;
    float4 o0[8], o1[8];
    #pragma unroll
    for (int j = 0; j < 8; j++) {
        o0[j] = make_float4(0.f, 0.f, 0.f, 0.f);
        o1[j] = make_float4(0.f, 0.f, 0.f, 0.f);
    }

    for (int kt = 0; kt < 64; kt++) {
        const int n0 = kt * 64;
        // load K tile
        #pragma unroll
        for (int r = 0; r < 8; r++) {
            int idx = tid + r * 256;
            int n = idx >> 5, d = idx & 31;
            sK[n * 36 + d] = g_qkv[(base + n0 + n) * DTOT + DK + d];
        }
        // load V tile (float4, rows contiguous -> coalesced)
        #pragma unroll
        for (int r = 0; r < 16; r++) {
            int i  = tid + r * 256;
            int n  = i >> 6;
            int c4 = (i & 63) * 4;
            *reinterpret_cast<float4*>(&sV[n * 256 + c4]) =
                *reinterpret_cast<const float4*>(
                    &g_qkv[(base + n0 + n) * DTOT + 2 * DK + c4]);
        }
        __syncthreads();

        // ---- S = Q K^T * scale, online softmax ----
        float s[16];
        float tmax = -1e30f;
        #pragma unroll
        for (int jn = 0; jn < 16; jn++) {
            int n = nq * 16 + jn;
            float4 a = make_float4(0.f, 0.f, 0.f, 0.f);
            #pragma unroll
            for (int d4 = 0; d4 < 8; d4++) {
                float4 k4 = *reinterpret_cast<const float4*>(&sK[n * 36 + 4 * d4]);
                a.x += q4[d4].x * k4.x; a.y += q4[d4].y * k4.y;
                a.z += q4[d4].z * k4.z; a.w += q4[d4].w * k4.w;
            }
            s[jn] = (a.x + a.y + a.z + a.w) * SCALE;
            tmax = fmaxf(tmax, s[jn]);
        }
        tmax = fmaxf(tmax, __shfl_xor_sync(0xffffffffu, tmax, 1));
        tmax = fmaxf(tmax, __shfl_xor_sync(0xffffffffu, tmax, 2));
        float Mnew  = fmaxf(Mrow, tmax);
        float alpha = __expf(Mrow - Mnew);
        float lsum  = 0.f;
        #pragma unroll
        for (int jn = 0; jn < 16; jn++) {
            float p = __expf(s[jn] - Mnew);
            lsum += p;
            sP[mS * 68 + nq * 16 + jn] = p;
        }
        lsum += __shfl_xor_sync(0xffffffffu, lsum, 1);
        lsum += __shfl_xor_sync(0xffffffffu, lsum, 2);
        Lrow = Lrow * alpha + lsum;
        Mrow = Mnew;
        if (nq == 0) sAlpha[mS] = alpha;
        __syncthreads();

        // ---- O = O*alpha + P V ----
        float a0 = sAlpha[pm], a1 = sAlpha[pm + 32];
        #pragma unroll
        for (int j = 0; j < 8; j++) {
            o0[j].x *= a0; o0[j].y *= a0; o0[j].z *= a0; o0[j].w *= a0;
            o1[j].x *= a1; o1[j].y *= a1; o1[j].z *= a1; o1[j].w *= a1;
        }
        #pragma unroll
        for (int n4 = 0; n4 < 16; n4++) {
            float4 p0 = *reinterpret_cast<const float4*>(&sP[pm * 68 + 4 * n4]);
            float4 p1 = *reinterpret_cast<const float4*>(&sP[(pm + 32) * 68 + 4 * n4]);
            const float* vb = &sV[(4 * n4) * 256 + cq * 32];
            pv_step(p0.x, p1.x, vb + 0 * 256, o0, o1);
            pv_step(p0.y, p1.y, vb + 1 * 256, o0, o1);
            pv_step(p0.z, p1.z, vb + 2 * 256, o0, o1);
            pv_step(p0.w, p1.w, vb + 3 * 256, o0, o1);
        }
        __syncthreads();
    }

    // ---- epilogue: normalize, transpose through smem, add residual ----
    if (nq == 0) sSum[mS] = Lrow;
    __syncthreads();
    float inv0 = 1.f / sSum[pm];
    float inv1 = 1.f / sSum[pm + 32];

    // stage O into sV as [c][m] (sV no longer needed)
    #pragma unroll
    for (int j = 0; j < 8; j++) {
        int c = cq * 32 + 4 * j;
        sV[(c + 0) * 64 + pm] = o0[j].x * inv0;
        sV[(c + 1) * 64 + pm] = o0[j].y * inv0;
        sV[(c + 2) * 64 + pm] = o0[j].z * inv0;
        sV[(c + 3) * 64 + pm] = o0[j].w * inv0;
        sV[(c + 0) * 64 + pm + 32] = o1[j].x * inv1;
        sV[(c + 1) * 64 + pm + 32] = o1[j].y * inv1;
        sV[(c + 2) * 64 + pm + 32] = o1[j].z * inv1;
        sV[(c + 3) * 64 + pm + 32] = o1[j].w * inv1;
    }
    __syncthreads();

    for (int idx = tid; idx < 64 * 256; idx += 256) {
        int c = idx >> 6, m = idx & 63;
        size_t g = (size_t)(b * C + c) * N + m0 + m;
        out[g] = sV[c * 64 + m] + x[g];
    }
}

// ----------------------------------------------------------------------------
extern "C" void kernel_launch(void* const* d_in, const int* in_sizes, int n_in,
                              void* d_out, int out_size)
{
    const float* x  = (const float*)d_in[0];
    const float* Wq = (const float*)d_in[1];
    const float* bq = (const float*)d_in[2];
    const float* Wk = (const float*)d_in[3];
    const float* bk = (const float*)d_in[4];
    const float* Wv = (const float*)d_in[5];
    const float* bv = (const float*)d_in[6];
    float* out = (float*)d_out;

    cudaFuncSetAttribute(flash_kernel,
                         cudaFuncAttributeMaxDynamicSharedMemorySize, SMEM_BYTES);

    proj_kernel<<<dim3(N / 64, DTOT / 64, B), 256>>>(x, Wq, bq, Wk, bk, Wv, bv);
    flash_kernel<<<dim3(N / 64, B), 256, SMEM_BYTES>>>(x, out);
}

// round 8
// speedup vs baseline: 6.6938x; 6.6938x over previous
#include <cuda_runtime.h>
#include <cuda_bf16.h>
#include <math.h>

// ============================================================================
// CrossAttention: B=4, C=256, N=4096, DK=32.
//   K1: fused QKV projection (fp32 compute, bf16 output scratch)
//   K2: flash attention with bf16 mma.sync.m16n8k16 tensor cores,
//       register-resident P, cp.async double-buffered K/V, residual epilogue.
// ============================================================================

#define DEV_INLINE __device__ __forceinline__

constexpr int B    = 4;
constexpr int C    = 256;
constexpr int N    = 4096;
constexpr int DK   = 32;
constexpr int DTOT = 320;                       // 32 q + 32 k + 256 v (bf16)
constexpr float SCALE = 0.17677669529663687f;   // 1/sqrt(32)
constexpr float KS = SCALE * 1.4426950408889634f;   // fold into exp2

// bf16 scratch: (B, N, 320) = 10.5 MB
__device__ __nv_bfloat16 g_qkv[(size_t)B * N * DTOT];

// ----------------------------------------------------------------------------
// Kernel 1: projection.  out[b][n][d] = sum_c W[d][c] * x[b][c][n] + bias[d]
// ----------------------------------------------------------------------------
__global__ __launch_bounds__(256) void proj_kernel(
    const float* __restrict__ x,
    const float* __restrict__ Wq, const float* __restrict__ bq,
    const float* __restrict__ Wk, const float* __restrict__ bk,
    const float* __restrict__ Wv, const float* __restrict__ bv)
{
    __shared__ float xs[64][64];   // [c][n]
    __shared__ float ws[64][64];   // [d][c]

    const int tid = threadIdx.x;
    const int n0  = blockIdx.x * 64;
    const int d0  = blockIdx.y * 64;
    const int b   = blockIdx.z;
    const int tn  = tid & 15;
    const int td  = tid >> 4;

    float acc[4][4];
    #pragma unroll
    for (int i = 0; i < 4; i++)
        #pragma unroll
        for (int j = 0; j < 4; j++) acc[i][j] = 0.f;

    for (int cc = 0; cc < C; cc += 64) {
        #pragma unroll
        for (int r = 0; r < 4; r++) {
            int i  = tid + r * 256;
            int c  = i >> 4;
            int nn = (i & 15) * 4;
            *reinterpret_cast<float4*>(&xs[c][nn]) =
                *reinterpret_cast<const float4*>(
                    &x[(size_t)(b * C + cc + c) * N + n0 + nn]);
        }
        #pragma unroll
        for (int r = 0; r < 4; r++) {
            int i  = tid + r * 256;
            int d  = i >> 4;
            int c4 = (i & 15) * 4;
            int gd = d0 + d;
            const float* src;
            if (gd < DK)            src = Wq + (size_t)gd * C;
            else if (gd < 2 * DK)   src = Wk + (size_t)(gd - DK) * C;
            else                    src = Wv + (size_t)(gd - 2 * DK) * C;
            *reinterpret_cast<float4*>(&ws[d][c4]) =
                *reinterpret_cast<const float4*>(&src[cc + c4]);
        }
        __syncthreads();

        #pragma unroll 4
        for (int c = 0; c < 64; c++) {
            float4 xv = *reinterpret_cast<const float4*>(&xs[c][4 * tn]);
            float xvv[4] = {xv.x, xv.y, xv.z, xv.w};
            float wv[4];
            #pragma unroll
            for (int j = 0; j < 4; j++) wv[j] = ws[4 * td + j][c];
            #pragma unroll
            for (int i = 0; i < 4; i++)
                #pragma unroll
                for (int j = 0; j < 4; j++) acc[i][j] += xvv[i] * wv[j];
        }
        __syncthreads();
    }

    float bias[4];
    #pragma unroll
    for (int j = 0; j < 4; j++) {
        int gd = d0 + 4 * td + j;
        bias[j] = (gd < DK) ? bq[gd] : (gd < 2 * DK) ? bk[gd - DK] : bv[gd - 2 * DK];
    }
    #pragma unroll
    for (int i = 0; i < 4; i++) {
        __nv_bfloat162 p0 = __floats2bfloat162_rn(acc[i][0] + bias[0], acc[i][1] + bias[1]);
        __nv_bfloat162 p1 = __floats2bfloat162_rn(acc[i][2] + bias[2], acc[i][3] + bias[3]);
        uint2 st;
        st.x = *reinterpret_cast<unsigned*>(&p0);
        st.y = *reinterpret_cast<unsigned*>(&p1);
        *reinterpret_cast<uint2*>(
            &g_qkv[((size_t)b * N + n0 + 4 * tn + i) * DTOT + d0 + 4 * td]) = st;
    }
}

// ----------------------------------------------------------------------------
// mma / ldmatrix / cp.async helpers
// ----------------------------------------------------------------------------
DEV_INLINE void mma16816(float* d, const unsigned* a, unsigned b0, unsigned b1) {
    asm volatile(
        "mma.sync.aligned.m16n8k16.row.col.f32.bf16.bf16.f32 "
        "{%0,%1,%2,%3}, {%4,%5,%6,%7}, {%8,%9}, {%0,%1,%2,%3};"
        : "+f"(d[0]), "+f"(d[1]), "+f"(d[2]), "+f"(d[3])
        : "r"(a[0]), "r"(a[1]), "r"(a[2]), "r"(a[3]), "r"(b0), "r"(b1));
}

DEV_INLINE void ldx4(unsigned* r, unsigned saddr) {
    asm volatile("ldmatrix.sync.aligned.m8n8.x4.shared.b16 {%0,%1,%2,%3}, [%4];"
                 : "=r"(r[0]), "=r"(r[1]), "=r"(r[2]), "=r"(r[3]) : "r"(saddr));
}

DEV_INLINE void ldx4t(unsigned* r, unsigned saddr) {
    asm volatile("ldmatrix.sync.aligned.m8n8.x4.trans.shared.b16 {%0,%1,%2,%3}, [%4];"
                 : "=r"(r[0]), "=r"(r[1]), "=r"(r[2]), "=r"(r[3]) : "r"(saddr));
}

DEV_INLINE void cp16(unsigned sdst, const void* gsrc) {
    asm volatile("cp.async.cg.shared.global [%0], [%1], 16;" :: "r"(sdst), "l"(gsrc));
}
DEV_INLINE void cp_commit() { asm volatile("cp.async.commit_group;"); }
DEV_INLINE void cp_wait1()  { asm volatile("cp.async.wait_group 1;"); }
DEV_INLINE void cp_wait0()  { asm volatile("cp.async.wait_group 0;"); }

DEV_INLINE float ex2f(float x) {
    float y;
    asm("ex2.approx.ftz.f32 %0, %1;" : "=f"(y) : "f"(x));
    return y;
}

DEV_INLINE unsigned pack_bf2(float lo, float hi) {
    __nv_bfloat162 h = __floats2bfloat162_rn(lo, hi);
    return *reinterpret_cast<unsigned*>(&h);
}

// ----------------------------------------------------------------------------
// Kernel 2: flash attention.
//   CTA = 64 query rows, 8 warps: warp w -> row block r=w&3 (16 rows),
//   channel half h=w>>2 (128 channels).  K-tile = 64 keys per iteration.
// smem (bf16, padded strides for conflict-free ldmatrix):
//   sQ[64][40], sK[2][64][40], sV[2][64][264]  -> 82944 B
// ----------------------------------------------------------------------------
constexpr int SQ_OFF  = 0;
constexpr int SK_OFF  = 5120;                  // 64*40*2
constexpr int SK_SZ   = 5120;
constexpr int SV_OFF  = SK_OFF + 2 * SK_SZ;    // 15360
constexpr int SV_SZ   = 64 * 264 * 2;          // 33792
constexpr int SMEM_BYTES = SV_OFF + 2 * SV_SZ; // 82944

__global__ __launch_bounds__(256) void flash_kernel(
    const float* __restrict__ x, float* __restrict__ out)
{
    extern __shared__ char smem[];
    const unsigned sbase = (unsigned)__cvta_generic_to_shared(smem);

    const int tid  = threadIdx.x;
    const int lane = tid & 31;
    const int warp = tid >> 5;
    const int r    = warp & 3;     // query row block (16 rows)
    const int h    = warp >> 2;    // channel half (128 ch)
    const int qrow0 = 16 * r;
    const int b    = blockIdx.y;
    const int m0   = blockIdx.x * 64;
    const size_t base = (size_t)b * N;

    // ldmatrix per-lane address pieces
    const int lrow  = ((lane >> 3) & 1) * 8 + (lane & 7); // row within 16-row group
    const int lcol8 = (lane >> 4) * 8;                    // 8-elem col group

    // ---- prologue: issue cp.async for K/V tile 0 (buf 0) ----
    {
        const int n0t = 0;
        // K: 64 rows x 32 bf16 (4x16B per row); one 16B per thread
        {
            int m = tid >> 2, part = tid & 3;
            cp16(sbase + SK_OFF + (m * 40 + part * 8) * 2,
                 &g_qkv[(base + n0t + m) * DTOT + DK + part * 8]);
        }
        // V: 64 rows x 256 bf16 (32x16B per row); 8x16B per thread
        #pragma unroll
        for (int i = 0; i < 8; i++) {
            int idx = tid + i * 256;
            int m = idx >> 5, part = idx & 31;
            cp16(sbase + SV_OFF + (m * 264 + part * 8) * 2,
                 &g_qkv[(base + n0t + m) * DTOT + 2 * DK + part * 8]);
        }
        cp_commit();
    }

    // ---- load Q tile (plain), 64 rows x 32 bf16 ----
    // NOTE: uint4 = 16 B = 8 bf16, matching the part*8 element stride.
    // (R2 bug: uint2 here loaded only 4 bf16, leaving half of sQ uninitialized.)
    {
        int m = tid >> 2, part = tid & 3;
        uint4 v = *reinterpret_cast<const uint4*>(
            &g_qkv[(base + m0 + m) * DTOT + part * 8]);
        *reinterpret_cast<uint4*>(smem + SQ_OFF + (m * 40 + part * 8) * 2) = v;
    }
    __syncthreads();

    // Q fragments: 2 ksteps of m16n8k16 A-frags (persistent)
    unsigned qf[2][4];
    #pragma unroll
    for (int t = 0; t < 2; t++)
        ldx4(qf[t], sbase + SQ_OFF + ((qrow0 + lrow) * 40 + 16 * t + lcol8) * 2);

    // O accumulators: 16 rows x 128 ch -> 16 n-tiles of m16n8
    float o[16][4];
    #pragma unroll
    for (int j = 0; j < 16; j++)
        #pragma unroll
        for (int i = 0; i < 4; i++) o[j][i] = 0.f;

    float m2a = -1e30f, m2b = -1e30f;   // running max in exp2 domain
    float La = 0.f, Lb = 0.f;

    for (int kt = 0; kt < 64; kt++) {
        const int buf = kt & 1;

        // prefetch next tile into buf^1
        if (kt < 63) {
            const int n0t = (kt + 1) * 64;
            const unsigned skd = sbase + SK_OFF + (buf ^ 1) * SK_SZ;
            const unsigned svd = sbase + SV_OFF + (buf ^ 1) * SV_SZ;
            {
                int m = tid >> 2, part = tid & 3;
                cp16(skd + (m * 40 + part * 8) * 2,
                     &g_qkv[(base + n0t + m) * DTOT + DK + part * 8]);
            }
            #pragma unroll
            for (int i = 0; i < 8; i++) {
                int idx = tid + i * 256;
                int m = idx >> 5, part = idx & 31;
                cp16(svd + (m * 264 + part * 8) * 2,
                     &g_qkv[(base + n0t + m) * DTOT + 2 * DK + part * 8]);
            }
            cp_commit();
            cp_wait1();
        } else {
            cp_wait0();
        }
        __syncthreads();

        const unsigned skb = sbase + SK_OFF + buf * SK_SZ;
        const unsigned svb = sbase + SV_OFF + buf * SV_SZ;

        // ---- S = Q K^T : 8 n-tiles (64 keys) x 2 ksteps ----
        float sacc[8][4];
        #pragma unroll
        for (int j = 0; j < 8; j++)
            #pragma unroll
            for (int i = 0; i < 4; i++) sacc[j][i] = 0.f;

        #pragma unroll
        for (int j2 = 0; j2 < 4; j2++) {
            unsigned k0[4], k1[4];
            ldx4(k0, skb + ((16 * j2 + lrow) * 40 + 0  + lcol8) * 2);
            ldx4(k1, skb + ((16 * j2 + lrow) * 40 + 16 + lcol8) * 2);
            mma16816(sacc[2 * j2],     qf[0], k0[0], k0[2]);
            mma16816(sacc[2 * j2],     qf[1], k1[0], k1[2]);
            mma16816(sacc[2 * j2 + 1], qf[0], k0[1], k0[3]);
            mma16816(sacc[2 * j2 + 1], qf[1], k1[1], k1[3]);
        }

        // ---- online softmax (rows a = lane>>2 and a+8; quad shfl reduce) ----
        float tma = -1e30f, tmb = -1e30f;
        #pragma unroll
        for (int j = 0; j < 8; j++) {
            tma = fmaxf(tma, fmaxf(sacc[j][0], sacc[j][1]));
            tmb = fmaxf(tmb, fmaxf(sacc[j][2], sacc[j][3]));
        }
        tma = fmaxf(tma, __shfl_xor_sync(0xffffffffu, tma, 1));
        tma = fmaxf(tma, __shfl_xor_sync(0xffffffffu, tma, 2));
        tmb = fmaxf(tmb, __shfl_xor_sync(0xffffffffu, tmb, 1));
        tmb = fmaxf(tmb, __shfl_xor_sync(0xffffffffu, tmb, 2));

        float m2a_new = fmaxf(m2a, KS * tma);
        float m2b_new = fmaxf(m2b, KS * tmb);
        float alpha_a = ex2f(m2a - m2a_new);
        float alpha_b = ex2f(m2b - m2b_new);
        m2a = m2a_new; m2b = m2b_new;

        #pragma unroll
        for (int j = 0; j < 16; j++) {
            o[j][0] *= alpha_a; o[j][1] *= alpha_a;
            o[j][2] *= alpha_b; o[j][3] *= alpha_b;
        }

        float la = 0.f, lb = 0.f;
        #pragma unroll
        for (int j = 0; j < 8; j++) {
            sacc[j][0] = ex2f(fmaf(KS, sacc[j][0], -m2a_new));
            sacc[j][1] = ex2f(fmaf(KS, sacc[j][1], -m2a_new));
            sacc[j][2] = ex2f(fmaf(KS, sacc[j][2], -m2b_new));
            sacc[j][3] = ex2f(fmaf(KS, sacc[j][3], -m2b_new));
            la += sacc[j][0] + sacc[j][1];
            lb += sacc[j][2] + sacc[j][3];
        }
        la += __shfl_xor_sync(0xffffffffu, la, 1);
        la += __shfl_xor_sync(0xffffffffu, la, 2);
        lb += __shfl_xor_sync(0xffffffffu, lb, 1);
        lb += __shfl_xor_sync(0xffffffffu, lb, 2);
        La = La * alpha_a + la;
        Lb = Lb * alpha_b + lb;

        // ---- O += P V : 4 ksteps (keys) x 16 channel-tiles ----
        #pragma unroll
        for (int t = 0; t < 4; t++) {
            unsigned pa[4];
            pa[0] = pack_bf2(sacc[2 * t][0],     sacc[2 * t][1]);
            pa[1] = pack_bf2(sacc[2 * t][2],     sacc[2 * t][3]);
            pa[2] = pack_bf2(sacc[2 * t + 1][0], sacc[2 * t + 1][1]);
            pa[3] = pack_bf2(sacc[2 * t + 1][2], sacc[2 * t + 1][3]);
            #pragma unroll
            for (int u = 0; u < 8; u++) {
                unsigned vf[4];
                ldx4t(vf, svb + ((16 * t + lrow) * 264 + h * 128 + 16 * u + lcol8) * 2);
                mma16816(o[2 * u],     pa, vf[0], vf[1]);
                mma16816(o[2 * u + 1], pa, vf[2], vf[3]);
            }
        }
        __syncthreads();
    }

    // ---- epilogue: normalize, stage transpose in smem, residual add ----
    const float inva = 1.f / La;
    const float invb = 1.f / Lb;
    const int qq = lane & 3;       // col pair within n-tile
    const int aa = lane >> 2;      // row within 8

    float* stage = reinterpret_cast<float*>(smem);   // [128][68] fp32
    #pragma unroll
    for (int ph = 0; ph < 2; ph++) {
        if (h == ph) {
            #pragma unroll
            for (int j = 0; j < 16; j++) {
                int c  = 8 * j + 2 * qq;
                int ma = qrow0 + aa;
                stage[(c + 0) * 68 + ma]     = o[j][0] * inva;
                stage[(c + 1) * 68 + ma]     = o[j][1] * inva;
                stage[(c + 0) * 68 + ma + 8] = o[j][2] * invb;
                stage[(c + 1) * 68 + ma + 8] = o[j][3] * invb;
            }
        }
        __syncthreads();
        #pragma unroll
        for (int i = 0; i < 8; i++) {
            int idx = tid + i * 256;        // 2048 float4 = 128 ch x 16
            int c = idx >> 4, m4 = (idx & 15) * 4;
            int gc = ph * 128 + c;
            size_t g = (size_t)(b * C + gc) * N + m0 + m4;
            float4 vv = *reinterpret_cast<const float4*>(&stage[c * 68 + m4]);
            float4 xv = *reinterpret_cast<const float4*>(&x[g]);
            vv.x += xv.x; vv.y += xv.y; vv.z += xv.z; vv.w += xv.w;
            *reinterpret_cast<float4*>(&out[g]) = vv;
        }
        __syncthreads();
    }
}

// ----------------------------------------------------------------------------
extern "C" void kernel_launch(void* const* d_in, const int* in_sizes, int n_in,
                              void* d_out, int out_size)
{
    const float* x  = (const float*)d_in[0];
    const float* Wq = (const float*)d_in[1];
    const float* bq = (const float*)d_in[2];
    const float* Wk = (const float*)d_in[3];
    const float* bk = (const float*)d_in[4];
    const float* Wv = (const float*)d_in[5];
    const float* bv = (const float*)d_in[6];
    float* out = (float*)d_out;

    cudaFuncSetAttribute(flash_kernel,
                         cudaFuncAttributeMaxDynamicSharedMemorySize, SMEM_BYTES);

    proj_kernel<<<dim3(N / 64, DTOT / 64, B), 256>>>(x, Wq, bq, Wk, bk, Wv, bv);
    flash_kernel<<<dim3(N / 64, B), 256, SMEM_BYTES>>>(x, out);
}

// round 9
// speedup vs baseline: 11.4526x; 1.7109x over previous
#include <cuda_runtime.h>
#include <cuda_fp16.h>
#include <math.h>

// ============================================================================
// CrossAttention: B=4, C=256, N=4096, DK=32.
//   K1: QKV projection on f16 tensor cores (f32 accum), f16 scratch out.
//   K2: flash attention, f16 mma; S-GEMM f32-D, PV-GEMM f16-D (reg diet ->
//       2 CTAs/SM), cp.async double-buffered K/V, residual epilogue.
// ============================================================================

#define DEV_INLINE __device__ __forceinline__

constexpr int B    = 4;
constexpr int C    = 256;
constexpr int N    = 4096;
constexpr int DK   = 32;
constexpr int DTOT = 320;                       // 32 q + 32 k + 256 v (f16)
constexpr float SCALE = 0.17677669529663687f;   // 1/sqrt(32)
constexpr float KS = SCALE * 1.4426950408889634f;   // fold into exp2

// f16 scratch: (B, N, 320) = 10.5 MB
__device__ __half g_qkv[(size_t)B * N * DTOT];

// ----------------------------------------------------------------------------
// mma / ldmatrix / cp.async helpers
// ----------------------------------------------------------------------------
DEV_INLINE void mma_s(float* d, const unsigned* a, unsigned b0, unsigned b1) {
    asm volatile(
        "mma.sync.aligned.m16n8k16.row.col.f32.f16.f16.f32 "
        "{%0,%1,%2,%3}, {%4,%5,%6,%7}, {%8,%9}, {%0,%1,%2,%3};"
        : "+f"(d[0]), "+f"(d[1]), "+f"(d[2]), "+f"(d[3])
        : "r"(a[0]), "r"(a[1]), "r"(a[2]), "r"(a[3]), "r"(b0), "r"(b1));
}

DEV_INLINE void mma_h(unsigned* d, const unsigned* a, unsigned b0, unsigned b1) {
    asm volatile(
        "mma.sync.aligned.m16n8k16.row.col.f16.f16.f16.f16 "
        "{%0,%1}, {%2,%3,%4,%5}, {%6,%7}, {%0,%1};"
        : "+r"(d[0]), "+r"(d[1])
        : "r"(a[0]), "r"(a[1]), "r"(a[2]), "r"(a[3]), "r"(b0), "r"(b1));
}

DEV_INLINE void ldx4(unsigned* r, unsigned saddr) {
    asm volatile("ldmatrix.sync.aligned.m8n8.x4.shared.b16 {%0,%1,%2,%3}, [%4];"
                 : "=r"(r[0]), "=r"(r[1]), "=r"(r[2]), "=r"(r[3]) : "r"(saddr));
}

DEV_INLINE void ldx4t(unsigned* r, unsigned saddr) {
    asm volatile("ldmatrix.sync.aligned.m8n8.x4.trans.shared.b16 {%0,%1,%2,%3}, [%4];"
                 : "=r"(r[0]), "=r"(r[1]), "=r"(r[2]), "=r"(r[3]) : "r"(saddr));
}

DEV_INLINE void cp16(unsigned sdst, const void* gsrc) {
    asm volatile("cp.async.cg.shared.global [%0], [%1], 16;" :: "r"(sdst), "l"(gsrc));
}
DEV_INLINE void cp_commit() { asm volatile("cp.async.commit_group;"); }
DEV_INLINE void cp_wait1()  { asm volatile("cp.async.wait_group 1;"); }
DEV_INLINE void cp_wait0()  { asm volatile("cp.async.wait_group 0;"); }

DEV_INLINE float ex2f(float x) {
    float y;
    asm("ex2.approx.ftz.f32 %0, %1;" : "=f"(y) : "f"(x));
    return y;
}

DEV_INLINE unsigned pack_h2(float lo, float hi) {
    __half2 h = __floats2half2_rn(lo, hi);
    return *reinterpret_cast<unsigned*>(&h);
}
DEV_INLINE unsigned hmul2u(unsigned a, unsigned s) {
    __half2 r = __hmul2(*reinterpret_cast<__half2*>(&a),
                        *reinterpret_cast<__half2*>(&s));
    return *reinterpret_cast<unsigned*>(&r);
}

DEV_INLINE float get_bias(int d, const float* bq, const float* bk, const float* bv) {
    return (d < DK) ? bq[d] : (d < 2 * DK) ? bk[d - DK] : bv[d - 2 * DK];
}

// ----------------------------------------------------------------------------
// Kernel 1: projection on tensor cores.
//   out[b][n][d] = sum_c W[d][c] * x[b][c][n] + bias[d]   -> f16, n-major
//   CTA = 64 n x 320 d, 8 warps: warp = (16 n rows) x (160 d half).
//   K-chunks of 32: xs[c][n] (A via trans-ldmatrix), ws[d][c] (B direct).
// ----------------------------------------------------------------------------
__global__ __launch_bounds__(256) void proj_kernel(
    const float* __restrict__ x,
    const float* __restrict__ Wq, const float* __restrict__ bq,
    const float* __restrict__ Wk, const float* __restrict__ bk,
    const float* __restrict__ Wv, const float* __restrict__ bv)
{
    __shared__ __half xs[32][72];    // [c][n], pad 72 -> conflict-free trans-ldsm
    __shared__ __half ws[320][40];   // [d][c], pad 40 -> conflict-free ldsm

    const int tid  = threadIdx.x;
    const int lane = tid & 31;
    const int warp = tid >> 5;
    const int wr   = warp & 3;        // n row-block (16 rows)
    const int dh   = (warp >> 2) * 160;  // d half
    const int n0   = blockIdx.x * 64;
    const int b    = blockIdx.y;

    const unsigned sx = (unsigned)__cvta_generic_to_shared(xs);
    const unsigned sw = (unsigned)__cvta_generic_to_shared(ws);

    // B-frag (non-trans) lane addressing
    const int lrow  = ((lane >> 3) & 1) * 8 + (lane & 7);
    const int lcol8 = (lane >> 4) * 8;
    // A-frag (trans) lane addressing
    const int trow  = ((lane >> 4) & 1) * 8 + (lane & 7);
    const int tcol  = ((lane >> 3) & 1) * 8;

    float acc[20][4];
    #pragma unroll
    for (int j = 0; j < 20; j++)
        #pragma unroll
        for (int i = 0; i < 4; i++) acc[j][i] = 0.f;

    for (int c0 = 0; c0 < C; c0 += 32) {
        // x chunk: 32 c x 64 n fp32 -> f16
        #pragma unroll
        for (int rep = 0; rep < 2; rep++) {
            int i  = tid + rep * 256;      // 512 float4
            int c  = i >> 4;
            int n4 = (i & 15) * 4;
            float4 v = *reinterpret_cast<const float4*>(
                &x[(size_t)(b * C + c0 + c) * N + n0 + n4]);
            __half2 h0 = __floats2half2_rn(v.x, v.y);
            __half2 h1 = __floats2half2_rn(v.z, v.w);
            uint2 st;
            st.x = *reinterpret_cast<unsigned*>(&h0);
            st.y = *reinterpret_cast<unsigned*>(&h1);
            *reinterpret_cast<uint2*>(&xs[c][n4]) = st;
        }
        // W chunk: 320 d x 32 c fp32 -> f16
        #pragma unroll
        for (int rep = 0; rep < 10; rep++) {
            int i  = tid + rep * 256;      // 2560 float4
            int d  = i >> 3;
            int c4 = (i & 7) * 4;
            const float* src;
            if (d < DK)            src = Wq + (size_t)d * C;
            else if (d < 2 * DK)   src = Wk + (size_t)(d - DK) * C;
            else                   src = Wv + (size_t)(d - 2 * DK) * C;
            float4 v = *reinterpret_cast<const float4*>(&src[c0 + c4]);
            __half2 h0 = __floats2half2_rn(v.x, v.y);
            __half2 h1 = __floats2half2_rn(v.z, v.w);
            uint2 st;
            st.x = *reinterpret_cast<unsigned*>(&h0);
            st.y = *reinterpret_cast<unsigned*>(&h1);
            *reinterpret_cast<uint2*>(&ws[d][c4]) = st;
        }
        __syncthreads();

        #pragma unroll
        for (int kk = 0; kk < 32; kk += 16) {
            unsigned a[4];
            ldx4t(a, sx + ((kk + trow) * 72 + 16 * wr + tcol) * 2);
            #pragma unroll
            for (int j2 = 0; j2 < 10; j2++) {
                unsigned w[4];
                ldx4(w, sw + ((dh + 16 * j2 + lrow) * 40 + kk + lcol8) * 2);
                mma_s(acc[2 * j2],     a, w[0], w[2]);
                mma_s(acc[2 * j2 + 1], a, w[1], w[3]);
            }
        }
        __syncthreads();
    }

    // epilogue: bias + f16 store
    const int r  = lane >> 2;
    const int q2 = 2 * (lane & 3);
    const size_t rowA = ((size_t)b * N + n0 + 16 * wr + r) * DTOT;
    const size_t rowB = rowA + 8 * (size_t)DTOT;
    #pragma unroll
    for (int j = 0; j < 20; j++) {
        int d = dh + 8 * j + q2;
        float b0 = get_bias(d, bq, bk, bv);
        float b1 = get_bias(d + 1, bq, bk, bv);
        __half2 va = __floats2half2_rn(acc[j][0] + b0, acc[j][1] + b1);
        __half2 vb = __floats2half2_rn(acc[j][2] + b0, acc[j][3] + b1);
        *reinterpret_cast<__half2*>(&g_qkv[rowA + d]) = va;
        *reinterpret_cast<__half2*>(&g_qkv[rowB + d]) = vb;
    }
}

// ----------------------------------------------------------------------------
// Kernel 2: flash attention.  CTA = 64 queries, 8 warps, 2 CTAs/SM.
// smem: sQ[64][40], sK[2][64][40], sV[2][64][264] (f16) -> 82944 B
// ----------------------------------------------------------------------------
constexpr int SQ_OFF  = 0;
constexpr int SK_OFF  = 5120;                  // 64*40*2
constexpr int SK_SZ   = 5120;
constexpr int SV_OFF  = SK_OFF + 2 * SK_SZ;    // 15360
constexpr int SV_SZ   = 64 * 264 * 2;          // 33792
constexpr int SMEM_BYTES = SV_OFF + 2 * SV_SZ; // 82944

__global__ __launch_bounds__(256, 2) void flash_kernel(
    const float* __restrict__ x, float* __restrict__ out)
{
    extern __shared__ char smem[];
    const unsigned sbase = (unsigned)__cvta_generic_to_shared(smem);

    const int tid  = threadIdx.x;
    const int lane = tid & 31;
    const int warp = tid >> 5;
    const int r    = warp & 3;     // query row block (16 rows)
    const int h    = warp >> 2;    // channel half (128 ch)
    const int qrow0 = 16 * r;
    const int b    = blockIdx.y;
    const int m0   = blockIdx.x * 64;
    const size_t base = (size_t)b * N;

    const int lrow  = ((lane >> 3) & 1) * 8 + (lane & 7);
    const int lcol8 = (lane >> 4) * 8;

    // ---- prologue: cp.async K/V tile 0 into buf 0 ----
    {
        {
            int m = tid >> 2, part = tid & 3;
            cp16(sbase + SK_OFF + (m * 40 + part * 8) * 2,
                 &g_qkv[(base + m) * DTOT + DK + part * 8]);
        }
        #pragma unroll
        for (int i = 0; i < 8; i++) {
            int idx = tid + i * 256;
            int m = idx >> 5, part = idx & 31;
            cp16(sbase + SV_OFF + (m * 264 + part * 8) * 2,
                 &g_qkv[(base + m) * DTOT + 2 * DK + part * 8]);
        }
        cp_commit();
    }

    // ---- load Q tile ----
    {
        int m = tid >> 2, part = tid & 3;
        uint4 v = *reinterpret_cast<const uint4*>(
            &g_qkv[(base + m0 + m) * DTOT + part * 8]);
        *reinterpret_cast<uint4*>(smem + SQ_OFF + (m * 40 + part * 8) * 2) = v;
    }
    __syncthreads();

    unsigned qf[2][4];
    #pragma unroll
    for (int t = 0; t < 2; t++)
        ldx4(qf[t], sbase + SQ_OFF + ((qrow0 + lrow) * 40 + 16 * t + lcol8) * 2);

    // O accumulators: f16x2, [tile][row-half]  (16 tiles x 2 = 32 regs)
    unsigned o[16][2];
    #pragma unroll
    for (int j = 0; j < 16; j++) { o[j][0] = 0u; o[j][1] = 0u; }

    float m2a = -1e30f, m2b = -1e30f;
    float La = 0.f, Lb = 0.f;

    for (int kt = 0; kt < 64; kt++) {
        const int buf = kt & 1;

        if (kt < 63) {
            const int n0t = (kt + 1) * 64;
            const unsigned skd = sbase + SK_OFF + (buf ^ 1) * SK_SZ;
            const unsigned svd = sbase + SV_OFF + (buf ^ 1) * SV_SZ;
            {
                int m = tid >> 2, part = tid & 3;
                cp16(skd + (m * 40 + part * 8) * 2,
                     &g_qkv[(base + n0t + m) * DTOT + DK + part * 8]);
            }
            #pragma unroll
            for (int i = 0; i < 8; i++) {
                int idx = tid + i * 256;
                int m = idx >> 5, part = idx & 31;
                cp16(svd + (m * 264 + part * 8) * 2,
                     &g_qkv[(base + n0t + m) * DTOT + 2 * DK + part * 8]);
            }
            cp_commit();
            cp_wait1();
        } else {
            cp_wait0();
        }
        __syncthreads();

        const unsigned skb = sbase + SK_OFF + buf * SK_SZ;
        const unsigned svb = sbase + SV_OFF + buf * SV_SZ;

        // ---- S = Q K^T (f32 accum) ----
        float sacc[8][4];
        #pragma unroll
        for (int j = 0; j < 8; j++)
            #pragma unroll
            for (int i = 0; i < 4; i++) sacc[j][i] = 0.f;

        #pragma unroll
        for (int j2 = 0; j2 < 4; j2++) {
            unsigned k0[4], k1[4];
            ldx4(k0, skb + ((16 * j2 + lrow) * 40 + 0  + lcol8) * 2);
            ldx4(k1, skb + ((16 * j2 + lrow) * 40 + 16 + lcol8) * 2);
            mma_s(sacc[2 * j2],     qf[0], k0[0], k0[2]);
            mma_s(sacc[2 * j2],     qf[1], k1[0], k1[2]);
            mma_s(sacc[2 * j2 + 1], qf[0], k0[1], k0[3]);
            mma_s(sacc[2 * j2 + 1], qf[1], k1[1], k1[3]);
        }

        // ---- online softmax ----
        float tma = -1e30f, tmb = -1e30f;
        #pragma unroll
        for (int j = 0; j < 8; j++) {
            tma = fmaxf(tma, fmaxf(sacc[j][0], sacc[j][1]));
            tmb = fmaxf(tmb, fmaxf(sacc[j][2], sacc[j][3]));
        }
        tma = fmaxf(tma, __shfl_xor_sync(0xffffffffu, tma, 1));
        tma = fmaxf(tma, __shfl_xor_sync(0xffffffffu, tma, 2));
        tmb = fmaxf(tmb, __shfl_xor_sync(0xffffffffu, tmb, 1));
        tmb = fmaxf(tmb, __shfl_xor_sync(0xffffffffu, tmb, 2));

        float m2a_new = fmaxf(m2a, KS * tma);
        float m2b_new = fmaxf(m2b, KS * tmb);
        float alpha_a = ex2f(m2a - m2a_new);
        float alpha_b = ex2f(m2b - m2b_new);
        m2a = m2a_new; m2b = m2b_new;

        unsigned ha = pack_h2(alpha_a, alpha_a);
        unsigned hb = pack_h2(alpha_b, alpha_b);
        #pragma unroll
        for (int j = 0; j < 16; j++) {
            o[j][0] = hmul2u(o[j][0], ha);
            o[j][1] = hmul2u(o[j][1], hb);
        }

        float la = 0.f, lb = 0.f;
        #pragma unroll
        for (int j = 0; j < 8; j++) {
            sacc[j][0] = ex2f(fmaf(KS, sacc[j][0], -m2a_new));
            sacc[j][1] = ex2f(fmaf(KS, sacc[j][1], -m2a_new));
            sacc[j][2] = ex2f(fmaf(KS, sacc[j][2], -m2b_new));
            sacc[j][3] = ex2f(fmaf(KS, sacc[j][3], -m2b_new));
            la += sacc[j][0] + sacc[j][1];
            lb += sacc[j][2] + sacc[j][3];
        }
        la += __shfl_xor_sync(0xffffffffu, la, 1);
        la += __shfl_xor_sync(0xffffffffu, la, 2);
        lb += __shfl_xor_sync(0xffffffffu, lb, 1);
        lb += __shfl_xor_sync(0xffffffffu, lb, 2);
        La = La * alpha_a + la;
        Lb = Lb * alpha_b + lb;

        // ---- O += P V (f16 accum) ----
        #pragma unroll
        for (int t = 0; t < 4; t++) {
            unsigned pa[4];
            pa[0] = pack_h2(sacc[2 * t][0],     sacc[2 * t][1]);
            pa[1] = pack_h2(sacc[2 * t][2],     sacc[2 * t][3]);
            pa[2] = pack_h2(sacc[2 * t + 1][0], sacc[2 * t + 1][1]);
            pa[3] = pack_h2(sacc[2 * t + 1][2], sacc[2 * t + 1][3]);
            #pragma unroll
            for (int u = 0; u < 8; u++) {
                unsigned vf[4];
                ldx4t(vf, svb + ((16 * t + lrow) * 264 + h * 128 + 16 * u + lcol8) * 2);
                mma_h(o[2 * u],     pa, vf[0], vf[1]);
                mma_h(o[2 * u + 1], pa, vf[2], vf[3]);
            }
        }
        __syncthreads();
    }

    // ---- epilogue: normalize, transpose via smem, residual add ----
    const float inva = 1.f / La;
    const float invb = 1.f / Lb;
    const int qq = lane & 3;
    const int aa = lane >> 2;

    float* stage = reinterpret_cast<float*>(smem);   // [128][68] fp32
    #pragma unroll
    for (int ph = 0; ph < 2; ph++) {
        if (h == ph) {
            #pragma unroll
            for (int j = 0; j < 16; j++) {
                int c  = 8 * j + 2 * qq;
                int ma = qrow0 + aa;
                __half2 va = *reinterpret_cast<__half2*>(&o[j][0]);
                __half2 vb = *reinterpret_cast<__half2*>(&o[j][1]);
                stage[(c + 0) * 68 + ma]     = __low2float(va)  * inva;
                stage[(c + 1) * 68 + ma]     = __high2float(va) * inva;
                stage[(c + 0) * 68 + ma + 8] = __low2float(vb)  * invb;
                stage[(c + 1) * 68 + ma + 8] = __high2float(vb) * invb;
            }
        }
        __syncthreads();
        #pragma unroll
        for (int i = 0; i < 8; i++) {
            int idx = tid + i * 256;
            int c = idx >> 4, m4 = (idx & 15) * 4;
            int gc = ph * 128 + c;
            size_t g = (size_t)(b * C + gc) * N + m0 + m4;
            float4 vv = *reinterpret_cast<const float4*>(&stage[c * 68 + m4]);
            float4 xv = *reinterpret_cast<const float4*>(&x[g]);
            vv.x += xv.x; vv.y += xv.y; vv.z += xv.z; vv.w += xv.w;
            *reinterpret_cast<float4*>(&out[g]) = vv;
        }
        __syncthreads();
    }
}

// ----------------------------------------------------------------------------
extern "C" void kernel_launch(void* const* d_in, const int* in_sizes, int n_in,
                              void* d_out, int out_size)
{
    const float* x  = (const float*)d_in[0];
    const float* Wq = (const float*)d_in[1];
    const float* bq = (const float*)d_in[2];
    const float* Wk = (const float*)d_in[3];
    const float* bk = (const float*)d_in[4];
    const float* Wv = (const float*)d_in[5];
    const float* bv = (const float*)d_in[6];
    float* out = (float*)d_out;

    cudaFuncSetAttribute(flash_kernel,
                         cudaFuncAttributeMaxDynamicSharedMemorySize, SMEM_BYTES);
    cudaFuncSetAttribute(flash_kernel,
                         cudaFuncAttributePreferredSharedMemoryCarveout, 100);

    proj_kernel<<<dim3(N / 64, B), 256>>>(x, Wq, bq, Wk, bk, Wv, bv);
    flash_kernel<<<dim3(N / 64, B), 256, SMEM_BYTES>>>(x, out);
}

// round 11
// speedup vs baseline: 12.1015x; 1.0567x over previous
#include <cuda_runtime.h>
#include <cuda_fp16.h>
#include <math.h>

// ============================================================================
// CrossAttention: B=4, C=256, N=4096, DK=32.
//   K1: QKV projection on f16 tensor cores (f32 accum), f16 scratch out.
//   K2: flash attention, 128-query CTAs (grid=128 -> 1 CTA/SM, single wave),
//       8 warps x (32 query rows, 128-ch half): every K/V ldmatrix feeds 2x
//       row-tiles (ldsm:mma = 4). f32-D S-GEMM, f16-D PV-GEMM, cp.async
//       double-buffered K/V, residual epilogue.
// ============================================================================

#define DEV_INLINE __device__ __forceinline__

constexpr int B    = 4;
constexpr int C    = 256;
constexpr int N    = 4096;
constexpr int DK   = 32;
constexpr int DTOT = 320;                       // 32 q + 32 k + 256 v (f16)
constexpr float SCALE = 0.17677669529663687f;   // 1/sqrt(32)
constexpr float KS = SCALE * 1.4426950408889634f;   // fold into exp2

// f16 scratch: (B, N, 320) = 10.5 MB
__device__ __half g_qkv[(size_t)B * N * DTOT];

// ----------------------------------------------------------------------------
// mma / ldmatrix / cp.async helpers
// ----------------------------------------------------------------------------
DEV_INLINE void mma_s(float* d, const unsigned* a, unsigned b0, unsigned b1) {
    asm volatile(
        "mma.sync.aligned.m16n8k16.row.col.f32.f16.f16.f32 "
        "{%0,%1,%2,%3}, {%4,%5,%6,%7}, {%8,%9}, {%0,%1,%2,%3};"
        : "+f"(d[0]), "+f"(d[1]), "+f"(d[2]), "+f"(d[3])
        : "r"(a[0]), "r"(a[1]), "r"(a[2]), "r"(a[3]), "r"(b0), "r"(b1));
}

DEV_INLINE void mma_h(unsigned* d, const unsigned* a, unsigned b0, unsigned b1) {
    asm volatile(
        "mma.sync.aligned.m16n8k16.row.col.f16.f16.f16.f16 "
        "{%0,%1}, {%2,%3,%4,%5}, {%6,%7}, {%0,%1};"
        : "+r"(d[0]), "+r"(d[1])
        : "r"(a[0]), "r"(a[1]), "r"(a[2]), "r"(a[3]), "r"(b0), "r"(b1));
}

DEV_INLINE void ldx4(unsigned* r, unsigned saddr) {
    asm volatile("ldmatrix.sync.aligned.m8n8.x4.shared.b16 {%0,%1,%2,%3}, [%4];"
                 : "=r"(r[0]), "=r"(r[1]), "=r"(r[2]), "=r"(r[3]) : "r"(saddr));
}

DEV_INLINE void ldx4t(unsigned* r, unsigned saddr) {
    asm volatile("ldmatrix.sync.aligned.m8n8.x4.trans.shared.b16 {%0,%1,%2,%3}, [%4];"
                 : "=r"(r[0]), "=r"(r[1]), "=r"(r[2]), "=r"(r[3]) : "r"(saddr));
}

DEV_INLINE void cp16(unsigned sdst, const void* gsrc) {
    asm volatile("cp.async.cg.shared.global [%0], [%1], 16;" :: "r"(sdst), "l"(gsrc));
}
DEV_INLINE void cp_commit() { asm volatile("cp.async.commit_group;"); }
DEV_INLINE void cp_wait1()  { asm volatile("cp.async.wait_group 1;"); }
DEV_INLINE void cp_wait0()  { asm volatile("cp.async.wait_group 0;"); }

DEV_INLINE float ex2f(float x) {
    float y;
    asm("ex2.approx.ftz.f32 %0, %1;" : "=f"(y) : "f"(x));
    return y;
}

DEV_INLINE unsigned pack_h2(float lo, float hi) {
    __half2 h = __floats2half2_rn(lo, hi);
    return *reinterpret_cast<unsigned*>(&h);
}
DEV_INLINE unsigned hmul2u(unsigned a, unsigned s) {
    __half2 r = __hmul2(*reinterpret_cast<__half2*>(&a),
                        *reinterpret_cast<__half2*>(&s));
    return *reinterpret_cast<unsigned*>(&r);
}

DEV_INLINE float get_bias(int d, const float* bq, const float* bk, const float* bv) {
    return (d < DK) ? bq[d] : (d < 2 * DK) ? bk[d - DK] : bv[d - 2 * DK];
}

// ----------------------------------------------------------------------------
// Kernel 1: projection on tensor cores (unchanged from R9).
// ----------------------------------------------------------------------------
__global__ __launch_bounds__(256) void proj_kernel(
    const float* __restrict__ x,
    const float* __restrict__ Wq, const float* __restrict__ bq,
    const float* __restrict__ Wk, const float* __restrict__ bk,
    const float* __restrict__ Wv, const float* __restrict__ bv)
{
    __shared__ __half xs[32][72];
    __shared__ __half ws[320][40];

    const int tid  = threadIdx.x;
    const int lane = tid & 31;
    const int warp = tid >> 5;
    const int wr   = warp & 3;
    const int dh   = (warp >> 2) * 160;
    const int n0   = blockIdx.x * 64;
    const int b    = blockIdx.y;

    const unsigned sx = (unsigned)__cvta_generic_to_shared(xs);
    const unsigned sw = (unsigned)__cvta_generic_to_shared(ws);

    const int lrow  = ((lane >> 3) & 1) * 8 + (lane & 7);
    const int lcol8 = (lane >> 4) * 8;
    const int trow  = ((lane >> 4) & 1) * 8 + (lane & 7);
    const int tcol  = ((lane >> 3) & 1) * 8;

    float acc[20][4];
    #pragma unroll
    for (int j = 0; j < 20; j++)
        #pragma unroll
        for (int i = 0; i < 4; i++) acc[j][i] = 0.f;

    for (int c0 = 0; c0 < C; c0 += 32) {
        #pragma unroll
        for (int rep = 0; rep < 2; rep++) {
            int i  = tid + rep * 256;
            int c  = i >> 4;
            int n4 = (i & 15) * 4;
            float4 v = *reinterpret_cast<const float4*>(
                &x[(size_t)(b * C + c0 + c) * N + n0 + n4]);
            __half2 h0 = __floats2half2_rn(v.x, v.y);
            __half2 h1 = __floats2half2_rn(v.z, v.w);
            uint2 st;
            st.x = *reinterpret_cast<unsigned*>(&h0);
            st.y = *reinterpret_cast<unsigned*>(&h1);
            *reinterpret_cast<uint2*>(&xs[c][n4]) = st;
        }
        #pragma unroll
        for (int rep = 0; rep < 10; rep++) {
            int i  = tid + rep * 256;
            int d  = i >> 3;
            int c4 = (i & 7) * 4;
            const float* src;
            if (d < DK)            src = Wq + (size_t)d * C;
            else if (d < 2 * DK)   src = Wk + (size_t)(d - DK) * C;
            else                   src = Wv + (size_t)(d - 2 * DK) * C;
            float4 v = *reinterpret_cast<const float4*>(&src[c0 + c4]);
            __half2 h0 = __floats2half2_rn(v.x, v.y);
            __half2 h1 = __floats2half2_rn(v.z, v.w);
            uint2 st;
            st.x = *reinterpret_cast<unsigned*>(&h0);
            st.y = *reinterpret_cast<unsigned*>(&h1);
            *reinterpret_cast<uint2*>(&ws[d][c4]) = st;
        }
        __syncthreads();

        #pragma unroll
        for (int kk = 0; kk < 32; kk += 16) {
            unsigned a[4];
            ldx4t(a, sx + ((kk + trow) * 72 + 16 * wr + tcol) * 2);
            #pragma unroll
            for (int j2 = 0; j2 < 10; j2++) {
                unsigned w[4];
                ldx4(w, sw + ((dh + 16 * j2 + lrow) * 40 + kk + lcol8) * 2);
                mma_s(acc[2 * j2],     a, w[0], w[2]);
                mma_s(acc[2 * j2 + 1], a, w[1], w[3]);
            }
        }
        __syncthreads();
    }

    const int r  = lane >> 2;
    const int q2 = 2 * (lane & 3);
    const size_t rowA = ((size_t)b * N + n0 + 16 * wr + r) * DTOT;
    const size_t rowB = rowA + 8 * (size_t)DTOT;
    #pragma unroll
    for (int j = 0; j < 20; j++) {
        int d = dh + 8 * j + q2;
        float b0 = get_bias(d, bq, bk, bv);
        float b1 = get_bias(d + 1, bq, bk, bv);
        __half2 va = __floats2half2_rn(acc[j][0] + b0, acc[j][1] + b1);
        __half2 vb = __floats2half2_rn(acc[j][2] + b0, acc[j][3] + b1);
        *reinterpret_cast<__half2*>(&g_qkv[rowA + d]) = va;
        *reinterpret_cast<__half2*>(&g_qkv[rowB + d]) = vb;
    }
}

// ----------------------------------------------------------------------------
// Kernel 2: flash attention, 128-query CTAs.
// smem: sQ[128][40], sK[2][64][40], sV[2][64][264] (f16) -> 88064 B
// Epilogue stage reuses smem as fp32 [128 ch][132 m].
// ----------------------------------------------------------------------------
constexpr int SQ_OFF  = 0;                     // 128*40*2 = 10240
constexpr int SK_OFF  = 10240;
constexpr int SK_SZ   = 5120;                  // 64*40*2
constexpr int SV_OFF  = SK_OFF + 2 * SK_SZ;    // 20480
constexpr int SV_SZ   = 64 * 264 * 2;          // 33792
constexpr int SMEM_BYTES = SV_OFF + 2 * SV_SZ; // 88064

__global__ __launch_bounds__(256) void flash_kernel(
    const float* __restrict__ x, float* __restrict__ out)
{
    extern __shared__ char smem[];
    const unsigned sbase = (unsigned)__cvta_generic_to_shared(smem);

    const int tid  = threadIdx.x;
    const int lane = tid & 31;
    const int warp = tid >> 5;
    const int rgrp = warp & 3;      // 32-row query group
    const int h    = warp >> 2;     // channel half (128 ch)
    const int qrow0 = 32 * rgrp;
    const int b    = blockIdx.y;
    const int m0   = blockIdx.x * 128;
    const size_t base = (size_t)b * N;

    const int lrow  = ((lane >> 3) & 1) * 8 + (lane & 7);
    const int lcol8 = (lane >> 4) * 8;

    // ---- prologue: cp.async K/V tile 0 into buf 0 ----
    {
        {
            int m = tid >> 2, part = tid & 3;
            cp16(sbase + SK_OFF + (m * 40 + part * 8) * 2,
                 &g_qkv[(base + m) * DTOT + DK + part * 8]);
        }
        #pragma unroll
        for (int i = 0; i < 8; i++) {
            int idx = tid + i * 256;
            int m = idx >> 5, part = idx & 31;
            cp16(sbase + SV_OFF + (m * 264 + part * 8) * 2,
                 &g_qkv[(base + m) * DTOT + 2 * DK + part * 8]);
        }
        cp_commit();
    }

    // ---- load Q tile: 128 rows x 32 f16 ----
    #pragma unroll
    for (int i = 0; i < 2; i++) {
        int idx = tid + i * 256;
        int m = idx >> 2, part = idx & 3;
        uint4 v = *reinterpret_cast<const uint4*>(
            &g_qkv[(base + m0 + m) * DTOT + part * 8]);
        *reinterpret_cast<uint4*>(smem + SQ_OFF + (m * 40 + part * 8) * 2) = v;
    }
    __syncthreads();

    // Q fragments: 2 row-tiles x 2 ksteps
    unsigned qf[2][2][4];
    #pragma unroll
    for (int g = 0; g < 2; g++)
        #pragma unroll
        for (int t = 0; t < 2; t++)
            ldx4(qf[g][t],
                 sbase + SQ_OFF + ((qrow0 + 16 * g + lrow) * 40 + 16 * t + lcol8) * 2);

    // O accumulators: 2 row-tiles x 16 ch-tiles x f16x2 pair = 64 regs
    unsigned o[2][16][2];
    #pragma unroll
    for (int g = 0; g < 2; g++)
        #pragma unroll
        for (int j = 0; j < 16; j++) { o[g][j][0] = 0u; o[g][j][1] = 0u; }

    float m2[2][2] = {{-1e30f, -1e30f}, {-1e30f, -1e30f}};
    float L[2][2]  = {{0.f, 0.f}, {0.f, 0.f}};

    for (int kt = 0; kt < 64; kt++) {
        const int buf = kt & 1;

        if (kt < 63) {
            const int n0t = (kt + 1) * 64;
            const unsigned skd = sbase + SK_OFF + (buf ^ 1) * SK_SZ;
            const unsigned svd = sbase + SV_OFF + (buf ^ 1) * SV_SZ;
            {
                int m = tid >> 2, part = tid & 3;
                cp16(skd + (m * 40 + part * 8) * 2,
                     &g_qkv[(base + n0t + m) * DTOT + DK + part * 8]);
            }
            #pragma unroll
            for (int i = 0; i < 8; i++) {
                int idx = tid + i * 256;
                int m = idx >> 5, part = idx & 31;
                cp16(svd + (m * 264 + part * 8) * 2,
                     &g_qkv[(base + n0t + m) * DTOT + 2 * DK + part * 8]);
            }
            cp_commit();
            cp_wait1();
        } else {
            cp_wait0();
        }
        __syncthreads();

        const unsigned skb = sbase + SK_OFF + buf * SK_SZ;
        const unsigned svb = sbase + SV_OFF + buf * SV_SZ;

        // ---- K fragments once, reused by both row-tiles ----
        unsigned kf[8][4];
        #pragma unroll
        for (int j2 = 0; j2 < 4; j2++) {
            ldx4(kf[2 * j2],     skb + ((16 * j2 + lrow) * 40 + 0  + lcol8) * 2);
            ldx4(kf[2 * j2 + 1], skb + ((16 * j2 + lrow) * 40 + 16 + lcol8) * 2);
        }

        unsigned pa[2][4][4];   // P as A-frags, per row-tile per 16-key kstep

        #pragma unroll
        for (int g = 0; g < 2; g++) {
            // ---- S = Q K^T (f32 accum) for this row-tile ----
            float sacc[8][4];
            #pragma unroll
            for (int j = 0; j < 8; j++)
                #pragma unroll
                for (int i = 0; i < 4; i++) sacc[j][i] = 0.f;

            #pragma unroll
            for (int j2 = 0; j2 < 4; j2++) {
                mma_s(sacc[2 * j2],     qf[g][0], kf[2 * j2][0],     kf[2 * j2][2]);
                mma_s(sacc[2 * j2],     qf[g][1], kf[2 * j2 + 1][0], kf[2 * j2 + 1][2]);
                mma_s(sacc[2 * j2 + 1], qf[g][0], kf[2 * j2][1],     kf[2 * j2][3]);
                mma_s(sacc[2 * j2 + 1], qf[g][1], kf[2 * j2 + 1][1], kf[2 * j2 + 1][3]);
            }

            // ---- online softmax ----
            float tma = -1e30f, tmb = -1e30f;
            #pragma unroll
            for (int j = 0; j < 8; j++) {
                tma = fmaxf(tma, fmaxf(sacc[j][0], sacc[j][1]));
                tmb = fmaxf(tmb, fmaxf(sacc[j][2], sacc[j][3]));
            }
            tma = fmaxf(tma, __shfl_xor_sync(0xffffffffu, tma, 1));
            tma = fmaxf(tma, __shfl_xor_sync(0xffffffffu, tma, 2));
            tmb = fmaxf(tmb, __shfl_xor_sync(0xffffffffu, tmb, 1));
            tmb = fmaxf(tmb, __shfl_xor_sync(0xffffffffu, tmb, 2));

            float mna = fmaxf(m2[g][0], KS * tma);
            float mnb = fmaxf(m2[g][1], KS * tmb);
            float alpha_a = ex2f(m2[g][0] - mna);
            float alpha_b = ex2f(m2[g][1] - mnb);
            m2[g][0] = mna; m2[g][1] = mnb;

            unsigned ha = pack_h2(alpha_a, alpha_a);
            unsigned hb = pack_h2(alpha_b, alpha_b);
            #pragma unroll
            for (int j = 0; j < 16; j++) {
                o[g][j][0] = hmul2u(o[g][j][0], ha);
                o[g][j][1] = hmul2u(o[g][j][1], hb);
            }

            float la = 0.f, lb = 0.f;
            #pragma unroll
            for (int j = 0; j < 8; j++) {
                sacc[j][0] = ex2f(fmaf(KS, sacc[j][0], -mna));
                sacc[j][1] = ex2f(fmaf(KS, sacc[j][1], -mna));
                sacc[j][2] = ex2f(fmaf(KS, sacc[j][2], -mnb));
                sacc[j][3] = ex2f(fmaf(KS, sacc[j][3], -mnb));
                la += sacc[j][0] + sacc[j][1];
                lb += sacc[j][2] + sacc[j][3];
            }
            la += __shfl_xor_sync(0xffffffffu, la, 1);
            la += __shfl_xor_sync(0xffffffffu, la, 2);
            lb += __shfl_xor_sync(0xffffffffu, lb, 1);
            lb += __shfl_xor_sync(0xffffffffu, lb, 2);
            L[g][0] = L[g][0] * alpha_a + la;
            L[g][1] = L[g][1] * alpha_b + lb;

            #pragma unroll
            for (int t = 0; t < 4; t++) {
                pa[g][t][0] = pack_h2(sacc[2 * t][0],     sacc[2 * t][1]);
                pa[g][t][1] = pack_h2(sacc[2 * t][2],     sacc[2 * t][3]);
                pa[g][t][2] = pack_h2(sacc[2 * t + 1][0], sacc[2 * t + 1][1]);
                pa[g][t][3] = pack_h2(sacc[2 * t + 1][2], sacc[2 * t + 1][3]);
            }
        }

        // ---- O += P V : each V fragment feeds BOTH row-tiles ----
        #pragma unroll
        for (int t = 0; t < 4; t++) {
            #pragma unroll
            for (int u = 0; u < 8; u++) {
                unsigned vf[4];
                ldx4t(vf, svb + ((16 * t + lrow) * 264 + h * 128 + 16 * u + lcol8) * 2);
                mma_h(o[0][2 * u],     pa[0][t], vf[0], vf[1]);
                mma_h(o[0][2 * u + 1], pa[0][t], vf[2], vf[3]);
                mma_h(o[1][2 * u],     pa[1][t], vf[0], vf[1]);
                mma_h(o[1][2 * u + 1], pa[1][t], vf[2], vf[3]);
            }
        }
        __syncthreads();
    }

    // ---- epilogue: normalize, transpose via smem, residual add ----
    const int qq = lane & 3;
    const int aa = lane >> 2;

    float* stage = reinterpret_cast<float*>(smem);   // [128 ch][132 m] fp32
    #pragma unroll
    for (int ph = 0; ph < 2; ph++) {
        if (h == ph) {
            #pragma unroll
            for (int g = 0; g < 2; g++) {
                float inva = 1.f / L[g][0];
                float invb = 1.f / L[g][1];
                int ma = qrow0 + 16 * g + aa;
                #pragma unroll
                for (int j = 0; j < 16; j++) {
                    int c = 8 * j + 2 * qq;
                    __half2 va = *reinterpret_cast<__half2*>(&o[g][j][0]);
                    __half2 vb = *reinterpret_cast<__half2*>(&o[g][j][1]);
                    stage[(c + 0) * 132 + ma]     = __low2float(va)  * inva;
                    stage[(c + 1) * 132 + ma]     = __high2float(va) * inva;
                    stage[(c + 0) * 132 + ma + 8] = __low2float(vb)  * invb;
                    stage[(c + 1) * 132 + ma + 8] = __high2float(vb) * invb;
                }
            }
        }
        __syncthreads();
        #pragma unroll
        for (int i = 0; i < 16; i++) {
            int idx = tid + i * 256;        // 4096 float4 = 128 ch x 32
            int c = idx >> 5, m4 = (idx & 31) * 4;
            int gc = ph * 128 + c;
            size_t g = (size_t)(b * C + gc) * N + m0 + m4;
            float4 vv = *reinterpret_cast<const float4*>(&stage[c * 132 + m4]);
            float4 xv = *reinterpret_cast<const float4*>(&x[g]);
            vv.x += xv.x; vv.y += xv.y; vv.z += xv.z; vv.w += xv.w;
            *reinterpret_cast<float4*>(&out[g]) = vv;
        }
        __syncthreads();
    }
}

// ----------------------------------------------------------------------------
extern "C" void kernel_launch(void* const* d_in, const int* in_sizes, int n_in,
                              void* d_out, int out_size)
{
    const float* x  = (const float*)d_in[0];
    const float* Wq = (const float*)d_in[1];
    const float* bq = (const float*)d_in[2];
    const float* Wk = (const float*)d_in[3];
    const float* bk = (const float*)d_in[4];
    const float* Wv = (const float*)d_in[5];
    const float* bv = (const float*)d_in[6];
    float* out = (float*)d_out;

    cudaFuncSetAttribute(flash_kernel,
                         cudaFuncAttributeMaxDynamicSharedMemorySize, SMEM_BYTES);
    cudaFuncSetAttribute(flash_kernel,
                         cudaFuncAttributePreferredSharedMemoryCarveout, 100);

    proj_kernel<<<dim3(N / 64, B), 256>>>(x, Wq, bq, Wk, bk, Wv, bv);
    flash_kernel<<<dim3(N / 128, B), 256, SMEM_BYTES>>>(x, out);
}

// round 12
// speedup vs baseline: 12.2317x; 1.0108x over previous
#include <cuda_runtime.h>
#include <cuda_fp16.h>
#include <math.h>

// ============================================================================
// CrossAttention: B=4, C=256, N=4096, DK=32.
//   K1: QKV projection on f16 tensor cores (f32 accum), f16 scratch out.
//   K2: flash attention, 128-query CTAs (grid=128, 1 CTA/SM, single wave),
//       8 warps x (32 query rows, 128-ch half). f32-D S-GEMM, f16-D PV-GEMM,
//       f16x2 exp (exp output IS the PV A-fragment), non-volatile mma so
//       ptxas can overlap tensor ops with the softmax chain, cp.async
//       double-buffered K/V, residual epilogue.
// ============================================================================

#define DEV_INLINE __device__ __forceinline__

constexpr int B    = 4;
constexpr int C    = 256;
constexpr int N    = 4096;
constexpr int DK   = 32;
constexpr int DTOT = 320;                       // 32 q + 32 k + 256 v (f16)
constexpr float SCALE = 0.17677669529663687f;   // 1/sqrt(32)
constexpr float KS = SCALE * 1.4426950408889634f;   // fold into exp2

// f16 scratch: (B, N, 320) = 10.5 MB
__device__ __half g_qkv[(size_t)B * N * DTOT];

// ----------------------------------------------------------------------------
// mma / ldmatrix / cp.async helpers
// ----------------------------------------------------------------------------
// NOTE: mma are pure register ops -> NOT volatile, so ptxas may schedule them
// across the softmax MUFU chain. ldmatrix stays volatile (smem ordering).
DEV_INLINE void mma_s(float* d, const unsigned* a, unsigned b0, unsigned b1) {
    asm("mma.sync.aligned.m16n8k16.row.col.f32.f16.f16.f32 "
        "{%0,%1,%2,%3}, {%4,%5,%6,%7}, {%8,%9}, {%0,%1,%2,%3};"
        : "+f"(d[0]), "+f"(d[1]), "+f"(d[2]), "+f"(d[3])
        : "r"(a[0]), "r"(a[1]), "r"(a[2]), "r"(a[3]), "r"(b0), "r"(b1));
}

DEV_INLINE void mma_h(unsigned* d, const unsigned* a, unsigned b0, unsigned b1) {
    asm("mma.sync.aligned.m16n8k16.row.col.f16.f16.f16.f16 "
        "{%0,%1}, {%2,%3,%4,%5}, {%6,%7}, {%0,%1};"
        : "+r"(d[0]), "+r"(d[1])
        : "r"(a[0]), "r"(a[1]), "r"(a[2]), "r"(a[3]), "r"(b0), "r"(b1));
}

DEV_INLINE void ldx4(unsigned* r, unsigned saddr) {
    asm volatile("ldmatrix.sync.aligned.m8n8.x4.shared.b16 {%0,%1,%2,%3}, [%4];"
                 : "=r"(r[0]), "=r"(r[1]), "=r"(r[2]), "=r"(r[3]) : "r"(saddr));
}

DEV_INLINE void ldx4t(unsigned* r, unsigned saddr) {
    asm volatile("ldmatrix.sync.aligned.m8n8.x4.trans.shared.b16 {%0,%1,%2,%3}, [%4];"
                 : "=r"(r[0]), "=r"(r[1]), "=r"(r[2]), "=r"(r[3]) : "r"(saddr));
}

DEV_INLINE void cp16(unsigned sdst, const void* gsrc) {
    asm volatile("cp.async.cg.shared.global [%0], [%1], 16;" :: "r"(sdst), "l"(gsrc));
}
DEV_INLINE void cp_commit() { asm volatile("cp.async.commit_group;"); }
DEV_INLINE void cp_wait1()  { asm volatile("cp.async.wait_group 1;"); }
DEV_INLINE void cp_wait0()  { asm volatile("cp.async.wait_group 0;"); }

DEV_INLINE float ex2f(float x) {
    float y;
    asm("ex2.approx.ftz.f32 %0, %1;" : "=f"(y) : "f"(x));
    return y;
}
DEV_INLINE unsigned h2ex2(unsigned a) {
    unsigned d;
    asm("ex2.approx.f16x2 %0, %1;" : "=r"(d) : "r"(a));
    return d;
}

DEV_INLINE unsigned pack_h2(float lo, float hi) {
    __half2 h = __floats2half2_rn(lo, hi);
    return *reinterpret_cast<unsigned*>(&h);
}
DEV_INLINE unsigned hmul2u(unsigned a, unsigned s) {
    __half2 r = __hmul2(*reinterpret_cast<__half2*>(&a),
                        *reinterpret_cast<__half2*>(&s));
    return *reinterpret_cast<unsigned*>(&r);
}
DEV_INLINE unsigned hadd2u(unsigned a, unsigned b) {
    __half2 r = __hadd2(*reinterpret_cast<__half2*>(&a),
                        *reinterpret_cast<__half2*>(&b));
    return *reinterpret_cast<unsigned*>(&r);
}

DEV_INLINE float get_bias(int d, const float* bq, const float* bk, const float* bv) {
    return (d < DK) ? bq[d] : (d < 2 * DK) ? bk[d - DK] : bv[d - 2 * DK];
}

// ----------------------------------------------------------------------------
// Kernel 1: projection on tensor cores (unchanged).
// ----------------------------------------------------------------------------
__global__ __launch_bounds__(256) void proj_kernel(
    const float* __restrict__ x,
    const float* __restrict__ Wq, const float* __restrict__ bq,
    const float* __restrict__ Wk, const float* __restrict__ bk,
    const float* __restrict__ Wv, const float* __restrict__ bv)
{
    __shared__ __half xs[32][72];
    __shared__ __half ws[320][40];

    const int tid  = threadIdx.x;
    const int lane = tid & 31;
    const int warp = tid >> 5;
    const int wr   = warp & 3;
    const int dh   = (warp >> 2) * 160;
    const int n0   = blockIdx.x * 64;
    const int b    = blockIdx.y;

    const unsigned sx = (unsigned)__cvta_generic_to_shared(xs);
    const unsigned sw = (unsigned)__cvta_generic_to_shared(ws);

    const int lrow  = ((lane >> 3) & 1) * 8 + (lane & 7);
    const int lcol8 = (lane >> 4) * 8;
    const int trow  = ((lane >> 4) & 1) * 8 + (lane & 7);
    const int tcol  = ((lane >> 3) & 1) * 8;

    float acc[20][4];
    #pragma unroll
    for (int j = 0; j < 20; j++)
        #pragma unroll
        for (int i = 0; i < 4; i++) acc[j][i] = 0.f;

    for (int c0 = 0; c0 < C; c0 += 32) {
        #pragma unroll
        for (int rep = 0; rep < 2; rep++) {
            int i  = tid + rep * 256;
            int c  = i >> 4;
            int n4 = (i & 15) * 4;
            float4 v = *reinterpret_cast<const float4*>(
                &x[(size_t)(b * C + c0 + c) * N + n0 + n4]);
            __half2 h0 = __floats2half2_rn(v.x, v.y);
            __half2 h1 = __floats2half2_rn(v.z, v.w);
            uint2 st;
            st.x = *reinterpret_cast<unsigned*>(&h0);
            st.y = *reinterpret_cast<unsigned*>(&h1);
            *reinterpret_cast<uint2*>(&xs[c][n4]) = st;
        }
        #pragma unroll
        for (int rep = 0; rep < 10; rep++) {
            int i  = tid + rep * 256;
            int d  = i >> 3;
            int c4 = (i & 7) * 4;
            const float* src;
            if (d < DK)            src = Wq + (size_t)d * C;
            else if (d < 2 * DK)   src = Wk + (size_t)(d - DK) * C;
            else                   src = Wv + (size_t)(d - 2 * DK) * C;
            float4 v = *reinterpret_cast<const float4*>(&src[c0 + c4]);
            __half2 h0 = __floats2half2_rn(v.x, v.y);
            __half2 h1 = __floats2half2_rn(v.z, v.w);
            uint2 st;
            st.x = *reinterpret_cast<unsigned*>(&h0);
            st.y = *reinterpret_cast<unsigned*>(&h1);
            *reinterpret_cast<uint2*>(&ws[d][c4]) = st;
        }
        __syncthreads();

        #pragma unroll
        for (int kk = 0; kk < 32; kk += 16) {
            unsigned a[4];
            ldx4t(a, sx + ((kk + trow) * 72 + 16 * wr + tcol) * 2);
            #pragma unroll
            for (int j2 = 0; j2 < 10; j2++) {
                unsigned w[4];
                ldx4(w, sw + ((dh + 16 * j2 + lrow) * 40 + kk + lcol8) * 2);
                mma_s(acc[2 * j2],     a, w[0], w[2]);
                mma_s(acc[2 * j2 + 1], a, w[1], w[3]);
            }
        }
        __syncthreads();
    }

    const int r  = lane >> 2;
    const int q2 = 2 * (lane & 3);
    const size_t rowA = ((size_t)b * N + n0 + 16 * wr + r) * DTOT;
    const size_t rowB = rowA + 8 * (size_t)DTOT;
    #pragma unroll
    for (int j = 0; j < 20; j++) {
        int d = dh + 8 * j + q2;
        float b0 = get_bias(d, bq, bk, bv);
        float b1 = get_bias(d + 1, bq, bk, bv);
        __half2 va = __floats2half2_rn(acc[j][0] + b0, acc[j][1] + b1);
        __half2 vb = __floats2half2_rn(acc[j][2] + b0, acc[j][3] + b1);
        *reinterpret_cast<__half2*>(&g_qkv[rowA + d]) = va;
        *reinterpret_cast<__half2*>(&g_qkv[rowB + d]) = vb;
    }
}

// ----------------------------------------------------------------------------
// Kernel 2: flash attention, 128-query CTAs.
// smem: sQ[128][40], sK[2][64][40], sV[2][64][264] (f16) -> 88064 B
// ----------------------------------------------------------------------------
constexpr int SQ_OFF  = 0;                     // 128*40*2 = 10240
constexpr int SK_OFF  = 10240;
constexpr int SK_SZ   = 5120;                  // 64*40*2
constexpr int SV_OFF  = SK_OFF + 2 * SK_SZ;    // 20480
constexpr int SV_SZ   = 64 * 264 * 2;          // 33792
constexpr int SMEM_BYTES = SV_OFF + 2 * SV_SZ; // 88064

__global__ __launch_bounds__(256) void flash_kernel(
    const float* __restrict__ x, float* __restrict__ out)
{
    extern __shared__ char smem[];
    const unsigned sbase = (unsigned)__cvta_generic_to_shared(smem);

    const int tid  = threadIdx.x;
    const int lane = tid & 31;
    const int warp = tid >> 5;
    const int rgrp = warp & 3;      // 32-row query group
    const int h    = warp >> 2;     // channel half (128 ch)
    const int qrow0 = 32 * rgrp;
    const int b    = blockIdx.y;
    const int m0   = blockIdx.x * 128;
    const size_t base = (size_t)b * N;

    const int lrow  = ((lane >> 3) & 1) * 8 + (lane & 7);
    const int lcol8 = (lane >> 4) * 8;

    // ---- prologue: cp.async K/V tile 0 into buf 0 ----
    {
        {
            int m = tid >> 2, part = tid & 3;
            cp16(sbase + SK_OFF + (m * 40 + part * 8) * 2,
                 &g_qkv[(base + m) * DTOT + DK + part * 8]);
        }
        #pragma unroll
        for (int i = 0; i < 8; i++) {
            int idx = tid + i * 256;
            int m = idx >> 5, part = idx & 31;
            cp16(sbase + SV_OFF + (m * 264 + part * 8) * 2,
                 &g_qkv[(base + m) * DTOT + 2 * DK + part * 8]);
        }
        cp_commit();
    }

    // ---- load Q tile: 128 rows x 32 f16 ----
    #pragma unroll
    for (int i = 0; i < 2; i++) {
        int idx = tid + i * 256;
        int m = idx >> 2, part = idx & 3;
        uint4 v = *reinterpret_cast<const uint4*>(
            &g_qkv[(base + m0 + m) * DTOT + part * 8]);
        *reinterpret_cast<uint4*>(smem + SQ_OFF + (m * 40 + part * 8) * 2) = v;
    }
    __syncthreads();

    // Q fragments: 2 row-tiles x 2 ksteps
    unsigned qf[2][2][4];
    #pragma unroll
    for (int g = 0; g < 2; g++)
        #pragma unroll
        for (int t = 0; t < 2; t++)
            ldx4(qf[g][t],
                 sbase + SQ_OFF + ((qrow0 + 16 * g + lrow) * 40 + 16 * t + lcol8) * 2);

    // O accumulators: 2 row-tiles x 16 ch-tiles x f16x2 pair = 64 regs
    unsigned o[2][16][2];
    #pragma unroll
    for (int g = 0; g < 2; g++)
        #pragma unroll
        for (int j = 0; j < 16; j++) { o[g][j][0] = 0u; o[g][j][1] = 0u; }

    float m2[2][2] = {{-1e30f, -1e30f}, {-1e30f, -1e30f}};
    float L[2][2]  = {{0.f, 0.f}, {0.f, 0.f}};

    for (int kt = 0; kt < 64; kt++) {
        const int buf = kt & 1;

        if (kt < 63) {
            const int n0t = (kt + 1) * 64;
            const unsigned skd = sbase + SK_OFF + (buf ^ 1) * SK_SZ;
            const unsigned svd = sbase + SV_OFF + (buf ^ 1) * SV_SZ;
            {
                int m = tid >> 2, part = tid & 3;
                cp16(skd + (m * 40 + part * 8) * 2,
                     &g_qkv[(base + n0t + m) * DTOT + DK + part * 8]);
            }
            #pragma unroll
            for (int i = 0; i < 8; i++) {
                int idx = tid + i * 256;
                int m = idx >> 5, part = idx & 31;
                cp16(svd + (m * 264 + part * 8) * 2,
                     &g_qkv[(base + n0t + m) * DTOT + 2 * DK + part * 8]);
            }
            cp_commit();
            cp_wait1();
        } else {
            cp_wait0();
        }
        __syncthreads();

        const unsigned skb = sbase + SK_OFF + buf * SK_SZ;
        const unsigned svb = sbase + SV_OFF + buf * SV_SZ;

        // ---- K fragments once, reused by both row-tiles ----
        unsigned kf[8][4];
        #pragma unroll
        for (int j2 = 0; j2 < 4; j2++) {
            ldx4(kf[2 * j2],     skb + ((16 * j2 + lrow) * 40 + 0  + lcol8) * 2);
            ldx4(kf[2 * j2 + 1], skb + ((16 * j2 + lrow) * 40 + 16 + lcol8) * 2);
        }

        // P (exp output) in f16x2; directly usable as PV A-fragments:
        //   pa[g][t] = { pha[g][2t], phb[g][2t], pha[g][2t+1], phb[g][2t+1] }
        unsigned pha[2][8], phb[2][8];

        #pragma unroll
        for (int g = 0; g < 2; g++) {
            // ---- S = Q K^T (f32 accum) for this row-tile ----
            float sacc[8][4];
            #pragma unroll
            for (int j = 0; j < 8; j++)
                #pragma unroll
                for (int i = 0; i < 4; i++) sacc[j][i] = 0.f;

            #pragma unroll
            for (int j2 = 0; j2 < 4; j2++) {
                mma_s(sacc[2 * j2],     qf[g][0], kf[2 * j2][0],     kf[2 * j2][2]);
                mma_s(sacc[2 * j2],     qf[g][1], kf[2 * j2 + 1][0], kf[2 * j2 + 1][2]);
                mma_s(sacc[2 * j2 + 1], qf[g][0], kf[2 * j2][1],     kf[2 * j2][3]);
                mma_s(sacc[2 * j2 + 1], qf[g][1], kf[2 * j2 + 1][1], kf[2 * j2 + 1][3]);
            }

            // ---- online softmax (f32 max, f16x2 exp) ----
            float tma = -1e30f, tmb = -1e30f;
            #pragma unroll
            for (int j = 0; j < 8; j++) {
                tma = fmaxf(tma, fmaxf(sacc[j][0], sacc[j][1]));
                tmb = fmaxf(tmb, fmaxf(sacc[j][2], sacc[j][3]));
            }
            tma = fmaxf(tma, __shfl_xor_sync(0xffffffffu, tma, 1));
            tma = fmaxf(tma, __shfl_xor_sync(0xffffffffu, tma, 2));
            tmb = fmaxf(tmb, __shfl_xor_sync(0xffffffffu, tmb, 1));
            tmb = fmaxf(tmb, __shfl_xor_sync(0xffffffffu, tmb, 2));

            float mna = fmaxf(m2[g][0], KS * tma);
            float mnb = fmaxf(m2[g][1], KS * tmb);
            float alpha_a = ex2f(m2[g][0] - mna);
            float alpha_b = ex2f(m2[g][1] - mnb);
            m2[g][0] = mna; m2[g][1] = mnb;

            unsigned ha2 = pack_h2(alpha_a, alpha_a);
            unsigned hb2 = pack_h2(alpha_b, alpha_b);
            #pragma unroll
            for (int j = 0; j < 16; j++) {
                o[g][j][0] = hmul2u(o[g][j][0], ha2);
                o[g][j][1] = hmul2u(o[g][j][1], hb2);
            }

            // p = ex2(KS*s - m) computed as f16x2; result IS the A-fragment
            #pragma unroll
            for (int j = 0; j < 8; j++) {
                float a0 = fmaf(KS, sacc[j][0], -mna);
                float a1 = fmaf(KS, sacc[j][1], -mna);
                float b0 = fmaf(KS, sacc[j][2], -mnb);
                float b1 = fmaf(KS, sacc[j][3], -mnb);
                pha[g][j] = h2ex2(pack_h2(a0, a1));
                phb[g][j] = h2ex2(pack_h2(b0, b1));
            }

            // row-sum via half2 tree (values <= 1, 8 terms -> safe), f32 finish
            unsigned sa01 = hadd2u(pha[g][0], pha[g][1]);
            unsigned sa23 = hadd2u(pha[g][2], pha[g][3]);
            unsigned sa45 = hadd2u(pha[g][4], pha[g][5]);
            unsigned sa67 = hadd2u(pha[g][6], pha[g][7]);
            unsigned saA  = hadd2u(hadd2u(sa01, sa23), hadd2u(sa45, sa67));
            unsigned sb01 = hadd2u(phb[g][0], phb[g][1]);
            unsigned sb23 = hadd2u(phb[g][2], phb[g][3]);
            unsigned sb45 = hadd2u(phb[g][4], phb[g][5]);
            unsigned sb67 = hadd2u(phb[g][6], phb[g][7]);
            unsigned sbB  = hadd2u(hadd2u(sb01, sb23), hadd2u(sb45, sb67));
            __half2 hva = *reinterpret_cast<__half2*>(&saA);
            __half2 hvb = *reinterpret_cast<__half2*>(&sbB);
            float la = __low2float(hva) + __high2float(hva);
            float lb = __low2float(hvb) + __high2float(hvb);
            la += __shfl_xor_sync(0xffffffffu, la, 1);
            la += __shfl_xor_sync(0xffffffffu, la, 2);
            lb += __shfl_xor_sync(0xffffffffu, lb, 1);
            lb += __shfl_xor_sync(0xffffffffu, lb, 2);
            L[g][0] = L[g][0] * alpha_a + la;
            L[g][1] = L[g][1] * alpha_b + lb;
        }

        // ---- O += P V : each V fragment feeds BOTH row-tiles ----
        #pragma unroll
        for (int t = 0; t < 4; t++) {
            unsigned pa0[4] = {pha[0][2 * t], phb[0][2 * t],
                               pha[0][2 * t + 1], phb[0][2 * t + 1]};
            unsigned pa1[4] = {pha[1][2 * t], phb[1][2 * t],
                               pha[1][2 * t + 1], phb[1][2 * t + 1]};
            #pragma unroll
            for (int u = 0; u < 8; u++) {
                unsigned vf[4];
                ldx4t(vf, svb + ((16 * t + lrow) * 264 + h * 128 + 16 * u + lcol8) * 2);
                mma_h(o[0][2 * u],     pa0, vf[0], vf[1]);
                mma_h(o[0][2 * u + 1], pa0, vf[2], vf[3]);
                mma_h(o[1][2 * u],     pa1, vf[0], vf[1]);
                mma_h(o[1][2 * u + 1], pa1, vf[2], vf[3]);
            }
        }
        __syncthreads();
    }

    // ---- epilogue: normalize, transpose via smem, residual add ----
    const int qq = lane & 3;
    const int aa = lane >> 2;

    float* stage = reinterpret_cast<float*>(smem);   // [128 ch][132 m] fp32
    #pragma unroll
    for (int ph = 0; ph < 2; ph++) {
        if (h == ph) {
            #pragma unroll
            for (int g = 0; g < 2; g++) {
                float inva = 1.f / L[g][0];
                float invb = 1.f / L[g][1];
                int ma = qrow0 + 16 * g + aa;
                #pragma unroll
                for (int j = 0; j < 16; j++) {
                    int c = 8 * j + 2 * qq;
                    __half2 va = *reinterpret_cast<__half2*>(&o[g][j][0]);
                    __half2 vb = *reinterpret_cast<__half2*>(&o[g][j][1]);
                    stage[(c + 0) * 132 + ma]     = __low2float(va)  * inva;
                    stage[(c + 1) * 132 + ma]     = __high2float(va) * inva;
                    stage[(c + 0) * 132 + ma + 8] = __low2float(vb)  * invb;
                    stage[(c + 1) * 132 + ma + 8] = __high2float(vb) * invb;
                }
            }
        }
        __syncthreads();
        #pragma unroll
        for (int i = 0; i < 16; i++) {
            int idx = tid + i * 256;        // 4096 float4 = 128 ch x 32
            int c = idx >> 5, m4 = (idx & 31) * 4;
            int gc = ph * 128 + c;
            size_t g = (size_t)(b * C + gc) * N + m0 + m4;
            float4 vv = *reinterpret_cast<const float4*>(&stage[c * 132 + m4]);
            float4 xv = *reinterpret_cast<const float4*>(&x[g]);
            vv.x += xv.x; vv.y += xv.y; vv.z += xv.z; vv.w += xv.w;
            *reinterpret_cast<float4*>(&out[g]) = vv;
        }
        __syncthreads();
    }
}

// ----------------------------------------------------------------------------
extern "C" void kernel_launch(void* const* d_in, const int* in_sizes, int n_in,
                              void* d_out, int out_size)
{
    const float* x  = (const float*)d_in[0];
    const float* Wq = (const float*)d_in[1];
    const float* bq = (const float*)d_in[2];
    const float* Wk = (const float*)d_in[3];
    const float* bk = (const float*)d_in[4];
    const float* Wv = (const float*)d_in[5];
    const float* bv = (const float*)d_in[6];
    float* out = (float*)d_out;

    cudaFuncSetAttribute(flash_kernel,
                         cudaFuncAttributeMaxDynamicSharedMemorySize, SMEM_BYTES);
    cudaFuncSetAttribute(flash_kernel,
                         cudaFuncAttributePreferredSharedMemoryCarveout, 100);

    proj_kernel<<<dim3(N / 64, B), 256>>>(x, Wq, bq, Wk, bk, Wv, bv);
    flash_kernel<<<dim3(N / 128, B), 256, SMEM_BYTES>>>(x, out);
}